// round 16
// baseline (speedup 1.0000x reference)
#include <cuda_runtime.h>
#include <cuda_bf16.h>
#include <cstdint>

#define INV_SQRT2 0.70710678118654752440f

#define E_DIM 512
#define A_DIM 128
#define T_DIM 64
#define R_DIM 16
#define MAX_E 100000
#define MAX_ATOMS 5000

// epilogue flags
#define F_ACT  1
#define F_RES  2
#define F_RES2 4
#define F_F32  8
#define F_BF   16
#define F_CMB  32
#define F_RBF  64

// weight-arena offsets (elements)
#define OFF_DENSE   0L
#define OFF_BA      262144L
#define OFF_DOWN    524288L
#define OFF_BIL     557056L
#define OFF_UPCA    622592L
#define OFF_UPAC    655360L
#define OFF_RESB0   688128L
#define OFF_RESB1   950272L
#define OFF_RESA0   1212416L
#define OFF_RESA1   1474560L
#define OFF_RESA2   1736704L
#define OFF_RESA3   1998848L
#define OFF_CONCAT  2260992L
#define OFF_RESM0   2654208L
#define OFF_RESM1   2916352L
#define W_ARENA     3178496L

// ------------------------------------------------------------------
// Scratch (device globals)
// ------------------------------------------------------------------
__device__ float g_A[(size_t)MAX_E * E_DIM];
__device__ float g_C[(size_t)MAX_E * E_DIM];
__device__ float g_mnew[(size_t)MAX_E * E_DIM];
__device__ float g_upac[(size_t)MAX_E * E_DIM];
__device__ float g_down[(size_t)MAX_E * T_DIM];
__device__ float g_atom[(size_t)MAX_ATOMS * E_DIM];
__device__ float g_hp2[(size_t)MAX_ATOMS * E_DIM];
__device__ float g_atomB[(size_t)MAX_ATOMS * A_DIM];
__device__ float g_atomC[(size_t)MAX_ATOMS * A_DIM];
__device__ float g_hnew[(size_t)MAX_ATOMS * A_DIM];
// bf16 hi/lo ping-pong activation buffers (max width 1024)
__device__ __nv_bfloat16 g_H0h[(size_t)MAX_E * 1024];
__device__ __nv_bfloat16 g_H0l[(size_t)MAX_E * 1024];
__device__ __nv_bfloat16 g_H1h[(size_t)MAX_E * 1024];
__device__ __nv_bfloat16 g_H1l[(size_t)MAX_E * 1024];
// transposed split weight arena [N][K] per weight
__device__ __nv_bfloat16 g_wBh[W_ARENA];
__device__ __nv_bfloat16 g_wBl[W_ARENA];

// ------------------------------------------------------------------
// Helpers
// ------------------------------------------------------------------
__device__ __forceinline__ float actf(float x) {
    return x * (1.0f / 0.6f) / (1.0f + __expf(-x));
}
__device__ __forceinline__ void split1(float v, __nv_bfloat16& h, __nv_bfloat16& l) {
    h = __float2bfloat16(v);
    l = __float2bfloat16(v - __bfloat162float(h));
}
__device__ __forceinline__ uint32_t smem_u32(const void* p) {
    uint32_t a;
    asm("{ .reg .u64 t; cvta.to.shared.u64 t, %1; cvt.u32.u64 %0, t; }" : "=r"(a) : "l"(p));
    return a;
}
__device__ __forceinline__ void ldm_x4(uint32_t& r0, uint32_t& r1, uint32_t& r2, uint32_t& r3, uint32_t a) {
    asm volatile("ldmatrix.sync.aligned.m8n8.x4.shared.b16 {%0,%1,%2,%3}, [%4];"
                 : "=r"(r0), "=r"(r1), "=r"(r2), "=r"(r3) : "r"(a));
}
__device__ __forceinline__ void mma_bf16(float* c, const uint32_t* a, const uint32_t* b) {
    asm volatile(
        "mma.sync.aligned.m16n8k16.row.col.f32.bf16.bf16.f32 "
        "{%0,%1,%2,%3}, {%4,%5,%6,%7}, {%8,%9}, {%0,%1,%2,%3};"
        : "+f"(c[0]), "+f"(c[1]), "+f"(c[2]), "+f"(c[3])
        : "r"(a[0]), "r"(a[1]), "r"(a[2]), "r"(a[3]), "r"(b[0]), "r"(b[1]));
}
__device__ __forceinline__ void cpa16(uint32_t dst, const void* src) {
    asm volatile("cp.async.cg.shared.global [%0], [%1], 16;" :: "r"(dst), "l"(src));
}
#define CP_COMMIT() asm volatile("cp.async.commit_group;" ::: "memory")
#define CP_WAIT(n)  asm volatile("cp.async.wait_group %0;" :: "n"(n) : "memory")

__device__ __forceinline__ unsigned long long pk2(float v) {
    unsigned long long r;
    unsigned u = __float_as_uint(v);
    asm("mov.b64 %0, {%1, %2};" : "=l"(r) : "r"(u), "r"(u));
    return r;
}
__device__ __forceinline__ void fma2(unsigned long long& a, unsigned long long x, unsigned long long y) {
    asm("fma.rn.f32x2 %0, %1, %2, %0;" : "+l"(a) : "l"(x), "l"(y));
}
__device__ __forceinline__ float2 up2(unsigned long long v) {
    unsigned lo, hi;
    asm("mov.b64 {%0, %1}, %2;" : "=r"(lo), "=r"(hi) : "l"(v));
    return make_float2(__uint_as_float(lo), __uint_as_float(hi));
}

// ------------------------------------------------------------------
// HMMA split-bf16 GEMM, cp.async 2-stage pipeline, 2 CTAs/SM.
// bh operand software-pipelined one ntp-pair ahead (2-slot rotation):
// MMAs consume bh loaded a full pair earlier (~96cyc cover) and bl at
// MMA #9 (~72cyc after its ldm), hiding the LDS latency that limited
// tensor throughput. HP is compile-time (concat launch only).
// ------------------------------------------------------------------
template <int NT, int HP>
__global__ void __launch_bounds__(256, 2) bgemm(
    const __nv_bfloat16* __restrict__ Ah, const __nv_bfloat16* __restrict__ Al,
    const __nv_bfloat16* __restrict__ Bh, const __nv_bfloat16* __restrict__ Bl,
    int M, int Nfull, int K, int flags,
    float* __restrict__ C, const float* __restrict__ res, const float* __restrict__ res2,
    const float* __restrict__ acbuf, const int* __restrict__ swapidx,
    const float* __restrict__ rbfA, const float* __restrict__ rbfW,
    const int* __restrict__ ida, const float* __restrict__ hp2,
    __nv_bfloat16* __restrict__ Ohi, __nv_bfloat16* __restrict__ Olo)
{
    constexpr int BN = NT * 16;
    constexpr int AS_ELE = 128 * 40;
    constexpr int BS_ELE = BN * 40;
    constexpr int STAGE = 2 * AS_ELE + 2 * BS_ELE;   // elements
    constexpr int BITER = (BN * 4) / 256;
    constexpr int PAIRS = NT / 2;
    extern __shared__ __nv_bfloat16 sm[];

    const int tid = threadIdx.x;
    const int lane = tid & 31, wid = tid >> 5;
    const int wm = (wid & 3) * 32;
    const int wn = (wid >> 2) * (NT * 8);
    const long brow = (long)blockIdx.y * 128;
    const long bcol = (long)blockIdx.x * BN;
    const uint32_t smb = smem_u32(sm);

    // ---- hoisted load addressing ----
    int ar0 = tid >> 2, aj = (tid & 3) * 8;
    int ar1 = ar0 + 64;
    long gr0 = brow + ar0; if (gr0 > (long)(M - 1)) gr0 = M - 1;
    long gr1 = brow + ar1; if (gr1 > (long)(M - 1)) gr1 = M - 1;
    const __nv_bfloat16* sAh0 = Ah + gr0 * (long)K + aj;
    const __nv_bfloat16* sAl0 = Al + gr0 * (long)K + aj;
    const __nv_bfloat16* sAh1 = Ah + gr1 * (long)K + aj;
    const __nv_bfloat16* sAl1 = Al + gr1 * (long)K + aj;
    const uint32_t dA0 = (uint32_t)(ar0 * 40) + aj;
    const uint32_t dA1 = (uint32_t)(ar1 * 40) + aj;
    const __nv_bfloat16* sBh[BITER];
    const __nv_bfloat16* sBl[BITER];
    uint32_t dB[BITER];
#pragma unroll
    for (int it = 0; it < BITER; it++) {
        int idx = tid + it * 256;
        int r = idx >> 2, j = (idx & 3) * 8;
        long gn = bcol + r;
        sBh[it] = Bh + gn * (long)K + j;
        sBl[it] = Bl + gn * (long)K + j;
        dB[it] = (uint32_t)(r * 40) + j;
    }

    auto load_chunk = [&](int k0, int s) {
        uint32_t sb = smb + (uint32_t)s * (STAGE * 2);
        cpa16(sb + dA0 * 2, sAh0 + k0);
        cpa16(sb + (AS_ELE + dA0) * 2, sAl0 + k0);
        cpa16(sb + dA1 * 2, sAh1 + k0);
        cpa16(sb + (AS_ELE + dA1) * 2, sAl1 + k0);
#pragma unroll
        for (int it = 0; it < BITER; it++) {
            cpa16(sb + (2 * AS_ELE + dB[it]) * 2, sBh[it] + k0);
            cpa16(sb + (2 * AS_ELE + BS_ELE + dB[it]) * 2, sBl[it] + k0);
        }
    };

    // ---- hoisted compute addressing ----
    const uint32_t aOff = (uint32_t)((wm + (lane & 15)) * 40) + (((lane >> 4) & 1) << 3);
    const uint32_t bOff = (uint32_t)((wn + (lane & 7) + (((lane >> 4) & 1) << 3)) * 40)
                        + (((lane >> 3) & 1) << 3);
    const uint32_t aB0 = smb + aOff * 2;
    const uint32_t aB1 = aB0 + STAGE * 2;
    const uint32_t bB0 = smb + (2 * AS_ELE + bOff) * 2;
    const uint32_t bB1 = bB0 + STAGE * 2;

    float acc[2][NT][4];
#pragma unroll
    for (int i = 0; i < 2; i++)
#pragma unroll
        for (int j = 0; j < NT; j++)
#pragma unroll
            for (int t = 0; t < 4; t++) acc[i][j][t] = 0.f;

    const int nc = K >> 5;

    load_chunk(0, 0);
    CP_COMMIT();

    for (int i = 0; i < nc; i++) {
        if (i + 1 < nc) {
            load_chunk((i + 1) << 5, (i + 1) & 1);
            CP_COMMIT();
            CP_WAIT(1);
        } else {
            CP_WAIT(0);
        }
        __syncthreads();

        const uint32_t aH = (i & 1) ? aB1 : aB0;
        const uint32_t bH = (i & 1) ? bB1 : bB0;

        uint32_t ah[2][4], al[2][4];
        uint32_t bh[2][4];
        // preload bh for (ks=0, pair 0)
        ldm_x4(bh[0][0], bh[0][1], bh[0][2], bh[0][3], bH);

#pragma unroll
        for (int it8 = 0; it8 < 2 * PAIRS; it8++) {
            const int ks = (it8 / PAIRS) << 4;
            const int ntp = (it8 % PAIRS) << 1;
            const int cur = it8 & 1, nxt = cur ^ 1;
            if ((it8 % PAIRS) == 0) {
                // load A operands for this ks
                ldm_x4(ah[0][0], ah[0][1], ah[0][2], ah[0][3], aH + ks * 2);
                ldm_x4(ah[1][0], ah[1][1], ah[1][2], ah[1][3], aH + (640 + ks) * 2);
                ldm_x4(al[0][0], al[0][1], al[0][2], al[0][3], aH + (AS_ELE + ks) * 2);
                ldm_x4(al[1][0], al[1][1], al[1][2], al[1][3], aH + (AS_ELE + 640 + ks) * 2);
            }
            uint32_t bl[4];
            ldm_x4(bl[0], bl[1], bl[2], bl[3], bH + (BS_ELE + ntp * 320 + ks) * 2);
            if (it8 + 1 < 2 * PAIRS) {
                const int nit = it8 + 1;
                const int nks = (nit / PAIRS) << 4;
                const int nntp = (nit % PAIRS) << 1;
                ldm_x4(bh[nxt][0], bh[nxt][1], bh[nxt][2], bh[nxt][3],
                       bH + (nntp * 320 + nks) * 2);
            }
            // bh[cur] was loaded a full pair earlier; bl first used at MMA #9
            mma_bf16(acc[0][ntp],     ah[0], bh[cur]);
            mma_bf16(acc[1][ntp],     ah[1], bh[cur]);
            mma_bf16(acc[0][ntp + 1], ah[0], bh[cur] + 2);
            mma_bf16(acc[1][ntp + 1], ah[1], bh[cur] + 2);
            mma_bf16(acc[0][ntp],     al[0], bh[cur]);
            mma_bf16(acc[1][ntp],     al[1], bh[cur]);
            mma_bf16(acc[0][ntp + 1], al[0], bh[cur] + 2);
            mma_bf16(acc[1][ntp + 1], al[1], bh[cur] + 2);
            mma_bf16(acc[0][ntp],     ah[0], bl);
            mma_bf16(acc[1][ntp],     ah[1], bl);
            mma_bf16(acc[0][ntp + 1], ah[0], bl + 2);
            mma_bf16(acc[1][ntp + 1], ah[1], bl + 2);
        }
        __syncthreads();
    }

    // ---- optional rbf SMEM tiles (post-mainloop; SMEM reused) ----
    float* srbf = (float*)sm;            // [128][16]
    float* sW   = (float*)sm + 2048;     // [16][BN]
    if (flags & F_RBF) {
        for (int idx = tid; idx < 2048; idx += 256) {
            int r = idx >> 4, t = idx & 15;
            long gr = brow + r;
            if (gr > (long)(M - 1)) gr = M - 1;
            srbf[idx] = rbfA[gr * 16 + t];
        }
        for (int idx = tid; idx < 16 * BN; idx += 256) {
            int t = idx / BN, c = idx - t * BN;
            sW[idx] = rbfW[(long)t * Nfull + bcol + c];
        }
        __syncthreads();
    }

    // ---- epilogue ----
#pragma unroll
    for (int mt = 0; mt < 2; mt++) {
#pragma unroll
        for (int nt = 0; nt < NT; nt++) {
            int lcol = wn + nt * 8 + (lane & 3) * 2;
            long col = bcol + lcol;
#pragma unroll
            for (int half = 0; half < 2; half++) {
                int lrow = wm + mt * 16 + (lane >> 2) + half * 8;
                long row = brow + lrow;
                if (row >= M) continue;
                float vx = acc[mt][nt][half * 2];
                float vy = acc[mt][nt][half * 2 + 1];
                long base = row * (long)Nfull + col;
                if (HP) {
                    long b1 = (long)swapidx[row] * Nfull + col;   // id_c gather -> hp1
                    long b2 = (long)ida[row] * Nfull + col;       // id_a gather -> hp2
                    float2 u = *(const float2*)&acbuf[b1];
                    float2 w = *(const float2*)&hp2[b2];
                    vx += u.x + w.x;
                    vy += u.y + w.y;
                }
                if (flags & F_ACT) { vx = actf(vx); vy = actf(vy); }
                if (flags & F_RBF) {
                    float rwx = 0.f, rwy = 0.f;
#pragma unroll
                    for (int t = 0; t < 16; t++) {
                        float rv = srbf[lrow * 16 + t];
                        rwx += rv * sW[t * BN + lcol];
                        rwy += rv * sW[t * BN + lcol + 1];
                    }
                    vx *= rwx; vy *= rwy;
                }
                if (flags & F_CMB) {
                    long sbase = (long)swapidx[row] * Nfull + col;
                    float2 a = *(const float2*)&acbuf[sbase];
                    float2 r = *(const float2*)&res[base];
                    vx = (r.x + (vx + a.x) * INV_SQRT2) * INV_SQRT2;
                    vy = (r.y + (vy + a.y) * INV_SQRT2) * INV_SQRT2;
                }
                if (flags & F_RES) {
                    float2 r = *(const float2*)&res[base];
                    vx = (r.x + vx) * INV_SQRT2;
                    vy = (r.y + vy) * INV_SQRT2;
                }
                if (flags & F_RES2) {
                    float2 r = *(const float2*)&res2[base];
                    vx = (r.x + vx) * INV_SQRT2;
                    vy = (r.y + vy) * INV_SQRT2;
                }
                if (flags & F_F32) *(float2*)&C[base] = make_float2(vx, vy);
                if (flags & F_BF) {
                    __nv_bfloat16 h0, l0, h1, l1;
                    split1(vx, h0, l0); split1(vy, h1, l1);
                    __nv_bfloat162 hp(h0, h1), lp(l0, l1);
                    *(__nv_bfloat162*)&Ohi[base] = hp;
                    *(__nv_bfloat162*)&Olo[base] = lp;
                }
            }
        }
    }
}

// ------------------------------------------------------------------
// fp32 SGEMM (small GEMMs): C = epi(A @ B)
// ------------------------------------------------------------------
__global__ void __launch_bounds__(256, 2) sgemm_kernel(
    const float* __restrict__ A, const float* __restrict__ B, float* __restrict__ C,
    int M, int N, int K, int flags,
    const float* __restrict__ res)
{
    __shared__ __align__(16) float As[8][128];
    __shared__ __align__(16) float Bs[8][128];
    int tid = threadIdx.x;
    int tx = tid & 15, ty = tid >> 4;
    long brow = (long)blockIdx.y * 128;
    long bcol = (long)blockIdx.x * 128;

    unsigned long long acc[8][4];
#pragma unroll
    for (int i = 0; i < 8; i++)
#pragma unroll
        for (int j = 0; j < 4; j++) acc[i][j] = 0ull;

    int aRow = tid >> 1, aCol = (tid & 1) * 4;
    int bRow = tid >> 5, bCol = (tid & 31) * 4;
    long aGr = brow + aRow;
    long bGc = bcol + bCol;

    for (int k0 = 0; k0 < K; k0 += 8) {
        float4 av = make_float4(0.f, 0.f, 0.f, 0.f);
        if (aGr < M) av = *reinterpret_cast<const float4*>(A + aGr * (long)K + (k0 + aCol));
        As[aCol + 0][aRow] = av.x;
        As[aCol + 1][aRow] = av.y;
        As[aCol + 2][aRow] = av.z;
        As[aCol + 3][aRow] = av.w;
        float4 bv = make_float4(0.f, 0.f, 0.f, 0.f);
        if (bGc < N) bv = *reinterpret_cast<const float4*>(B + (long)(k0 + bRow) * N + bGc);
        *reinterpret_cast<float4*>(&Bs[bRow][bCol]) = bv;
        __syncthreads();
#pragma unroll
        for (int kk = 0; kk < 8; kk++) {
            float4 a0 = *reinterpret_cast<const float4*>(&As[kk][ty * 8]);
            float4 a1 = *reinterpret_cast<const float4*>(&As[kk][ty * 8 + 4]);
            ulonglong2 b0 = *reinterpret_cast<const ulonglong2*>(&Bs[kk][tx * 8]);
            ulonglong2 b1 = *reinterpret_cast<const ulonglong2*>(&Bs[kk][tx * 8 + 4]);
            unsigned long long bb[4] = {b0.x, b0.y, b1.x, b1.y};
            float ra[8] = {a0.x, a0.y, a0.z, a0.w, a1.x, a1.y, a1.z, a1.w};
#pragma unroll
            for (int i = 0; i < 8; i++) {
                unsigned long long a2 = pk2(ra[i]);
#pragma unroll
                for (int j = 0; j < 4; j++) fma2(acc[i][j], a2, bb[j]);
            }
        }
        __syncthreads();
    }

#pragma unroll
    for (int i = 0; i < 8; i++) {
        long row = brow + ty * 8 + i;
        if (row >= M) continue;
#pragma unroll
        for (int j = 0; j < 4; j++) {
            long col = bcol + tx * 8 + j * 2;
            if (col >= N) continue;
            float2 v = up2(acc[i][j]);
            long idx = row * (long)N + col;
            if (flags & F_ACT) { v.x = actf(v.x); v.y = actf(v.y); }
            if (flags & F_RES) {
                v.x = (res[idx] + v.x) * INV_SQRT2;
                v.y = (res[idx + 1] + v.y) * INV_SQRT2;
            }
            C[idx] = v.x;
            C[idx + 1] = v.y;
        }
    }
}

// ------------------------------------------------------------------
// Conversions
// ------------------------------------------------------------------
__global__ void convertA_kernel(const float* __restrict__ x,
                                __nv_bfloat16* __restrict__ hi, __nv_bfloat16* __restrict__ lo, long n)
{
    long i = (long)blockIdx.x * blockDim.x + threadIdx.x;
    if (i >= n) return;
    __nv_bfloat16 h, l;
    split1(x[i], h, l);
    hi[i] = h; lo[i] = l;
}

// Batched weight conversion: all 15 weights in one launch.
struct WPtrs { const float* p[15]; };

__global__ void convAllW(WPtrs w, __nv_bfloat16* __restrict__ hi, __nv_bfloat16* __restrict__ lo)
{
    static const int KT[15] = {512, 512, 512, 1024, 64, 64, 512, 512, 512, 512, 512, 512, 512, 512, 512};
    static const int NT_[15] = {512, 512, 64, 64, 512, 512, 512, 512, 512, 512, 512, 512, 512, 512, 512};
    static const long OFF[15] = {OFF_DENSE, OFF_BA, OFF_DOWN, OFF_BIL, OFF_UPCA, OFF_UPAC,
                                 OFF_RESB0, OFF_RESB1, OFF_RESA0, OFF_RESA1, OFF_RESA2, OFF_RESA3,
                                 OFF_CONCAT, OFF_RESM0, OFF_RESM1};
    int j = blockIdx.y;
    int K = KT[j], N = NT_[j];
    long tot = (long)K * N;
    long i = (long)blockIdx.x * blockDim.x + threadIdx.x;
    if (i >= tot) return;
    int n = (int)(i / K), k = (int)(i - (long)n * K);
    __nv_bfloat16 h, l;
    split1(w.p[j][(long)k * N + n], h, l);
    hi[OFF[j] + i] = h;
    lo[OFF[j] + i] = l;
}

// ------------------------------------------------------------------
// Triplet kernel: 2 edges per block (128 threads); packed uint4 stores.
// ------------------------------------------------------------------
__global__ void __launch_bounds__(128) triplet_kernel(
    const float* __restrict__ xd, const float* __restrict__ sph,
    const float* __restrict__ cW, const int* __restrict__ ba,
    __nv_bfloat16* __restrict__ rWh, __nv_bfloat16* __restrict__ rWl, int nE)
{
    const int g = threadIdx.x >> 6;      // edge slot 0/1
    const int t = threadIdx.x & 63;
    const long e = (long)blockIdx.x * 2 + g;

    __shared__ float s_sph[2][70];
    __shared__ float s_cW[2][112];
    __shared__ int s_ba[2][10];

    if (e < nE) {
        if (t < 10) s_ba[g][t] = ba[e * 10 + t];
        for (int i = t; i < 70; i += 64) s_sph[g][i] = sph[e * 70 + i];
        for (int i = t; i < 112; i += 64) s_cW[g][i] = cW[e * 112 + i];
    }
    __syncthreads();
    if (e >= nE) return;

    float xv[10];
#pragma unroll
    for (int k = 0; k < 10; k++)
        xv[k] = xd[(long)s_ba[g][k] * 64 + t];

    float sk[7];
#pragma unroll
    for (int s = 0; s < 7; s++) {
        float a = 0.f;
#pragma unroll
        for (int k = 0; k < 10; k++) a += s_sph[g][k * 7 + s] * xv[k];
        sk[s] = a;
    }

    __nv_bfloat16 hbuf[16], lbuf[16];
#pragma unroll
    for (int j = 0; j < 16; j++) {
        float a = 0.f;
#pragma unroll
        for (int s = 0; s < 7; s++) a += s_cW[g][j * 7 + s] * sk[s];
        split1(a, hbuf[j], lbuf[j]);
    }
    long ob = e * 1024 + t * 16;
    *(uint4*)&rWh[ob]     = *(uint4*)&hbuf[0];
    *(uint4*)&rWh[ob + 8] = *(uint4*)&hbuf[8];
    *(uint4*)&rWl[ob]     = *(uint4*)&lbuf[0];
    *(uint4*)&rWl[ob + 8] = *(uint4*)&lbuf[8];
}

// ------------------------------------------------------------------
// Fused rbf_h MLP + scatter
// ------------------------------------------------------------------
__global__ void __launch_bounds__(256) scatter_fused(
    const float* __restrict__ mnew, const float* __restrict__ rbf_h,
    const float* __restrict__ W,   // [16][512]
    const int* __restrict__ id_a, float* __restrict__ atom, int nE)
{
    __shared__ float sW[16 * 256];
    __shared__ float srbf[64 * 16];
    __shared__ int sida[64];

    const int tid = threadIdx.x;
    const int chalf = blockIdx.y;
    const long e0 = (long)blockIdx.x * 64;

    for (int idx = tid; idx < 4096; idx += 256) {
        int t = idx >> 8, c = idx & 255;
        sW[idx] = W[t * 512 + chalf * 256 + c];
    }
    for (int idx = tid; idx < 1024; idx += 256) {
        int el = idx >> 4, t = idx & 15;
        long eg = e0 + el;
        srbf[idx] = (eg < nE) ? rbf_h[eg * 16 + t] : 0.f;
    }
    if (tid < 64) {
        long eg = e0 + tid;
        sida[tid] = (eg < nE) ? id_a[eg] : 0;
    }
    __syncthreads();

    const int c = tid;
    int nel = (int)(((long)nE - e0) < 64 ? (nE - e0) : 64);
    for (int el = 0; el < nel; el++) {
        long eg = e0 + el;
        float rw = 0.f;
#pragma unroll
        for (int t = 0; t < 16; t++) rw += srbf[el * 16 + t] * sW[t * 256 + c];
        float v = mnew[eg * 512 + chalf * 256 + c] * rw;
        atomicAdd(&atom[(long)sida[el] * 512 + chalf * 256 + c], v);
    }
}

// ------------------------------------------------------------------
// Remaining elementwise kernels
// ------------------------------------------------------------------
__global__ void zero_kernel(float* __restrict__ p, long n)
{
    long i = (long)blockIdx.x * blockDim.x + threadIdx.x;
    if (i < n) p[i] = 0.f;
}

__global__ void hnew_kernel(const float* __restrict__ h, const float* __restrict__ xa,
                            float* __restrict__ hnew, float* __restrict__ out, long n)
{
    long i = (long)blockIdx.x * blockDim.x + threadIdx.x;
    if (i >= n) return;
    float v = (h[i] + xa[i]) * INV_SQRT2;
    hnew[i] = v;
    out[i] = v;
}

// ------------------------------------------------------------------
// Host orchestration
// ------------------------------------------------------------------
static inline void sg(const float* A, const float* B, float* C, int M, int N, int K,
                      int flags, const float* res = nullptr)
{
    dim3 grid((N + 127) / 128, (M + 127) / 128);
    sgemm_kernel<<<grid, 256>>>(A, B, C, M, N, K, flags, res);
}

#define SMEM8 ((2 * 128 * 40 + 2 * 128 * 40) * 2 * 2)  // 81920 B
#define SMEM4 ((2 * 128 * 40 + 2 * 64 * 40) * 2 * 2)   // 61440 B

extern "C" void kernel_launch(void* const* d_in, const int* in_sizes, int n_in,
                              void* d_out, int out_size)
{
    const float* h_in       = (const float*)d_in[0];
    const float* m_in       = (const float*)d_in[1];
    const float* rbf3       = (const float*)d_in[2];
    const float* cbfW1      = (const float*)d_in[3];
    const float* sph        = (const float*)d_in[4];
    const float* rbf_h      = (const float*)d_in[5];
    const float* W_dense_ca = (const float*)d_in[6];
    const float* W_ba       = (const float*)d_in[7];
    const float* W_rbf3     = (const float*)d_in[8];
    const float* W_down     = (const float*)d_in[9];
    const float* W_bil      = (const float*)d_in[10];
    const float* W_up_ca    = (const float*)d_in[11];
    const float* W_up_ac    = (const float*)d_in[12];
    const float* W_res_b    = (const float*)d_in[13];
    const float* W_res_a    = (const float*)d_in[14];
    const float* W_rbf_hW   = (const float*)d_in[15];
    const float* W_atom_d   = (const float*)d_in[16];
    const float* W_atom_r   = (const float*)d_in[17];
    const float* W_concat   = (const float*)d_in[18];
    const float* W_res_m    = (const float*)d_in[19];
    const int* id_swap = (const int*)d_in[21];
    const int* id3_ba  = (const int*)d_in[22];
    const int* id_c    = (const int*)d_in[24];
    const int* id_a    = (const int*)d_in[25];

    int nE = in_sizes[1] / E_DIM;
    int nA = in_sizes[0] / A_DIM;
    float* out = (float*)d_out;

    float *pA, *pC, *pmnew, *pupac, *pdown;
    float *patom, *php2, *patomB, *patomC, *phnew;
    __nv_bfloat16 *H0h, *H0l, *H1h, *H1l, *wBh, *wBl;
    cudaGetSymbolAddress((void**)&pA, g_A);
    cudaGetSymbolAddress((void**)&pC, g_C);
    cudaGetSymbolAddress((void**)&pmnew, g_mnew);
    cudaGetSymbolAddress((void**)&pupac, g_upac);
    cudaGetSymbolAddress((void**)&pdown, g_down);
    cudaGetSymbolAddress((void**)&patom, g_atom);
    cudaGetSymbolAddress((void**)&php2, g_hp2);
    cudaGetSymbolAddress((void**)&patomB, g_atomB);
    cudaGetSymbolAddress((void**)&patomC, g_atomC);
    cudaGetSymbolAddress((void**)&phnew, g_hnew);
    cudaGetSymbolAddress((void**)&H0h, g_H0h);
    cudaGetSymbolAddress((void**)&H0l, g_H0l);
    cudaGetSymbolAddress((void**)&H1h, g_H1h);
    cudaGetSymbolAddress((void**)&H1l, g_H1l);
    cudaGetSymbolAddress((void**)&wBh, g_wBh);
    cudaGetSymbolAddress((void**)&wBl, g_wBl);

    cudaFuncSetAttribute((bgemm<8, 0>), cudaFuncAttributeMaxDynamicSharedMemorySize, SMEM8);
    cudaFuncSetAttribute((bgemm<8, 1>), cudaFuncAttributeMaxDynamicSharedMemorySize, SMEM8);
    cudaFuncSetAttribute((bgemm<4, 0>), cudaFuncAttributeMaxDynamicSharedMemorySize, SMEM4);

    long nME = (long)nE * E_DIM;
    int TB = 256;
    long gME = (nME + TB - 1) / TB;

    auto tc128 = [&](const __nv_bfloat16* Ahp, const __nv_bfloat16* Alp, long woff,
                     int M, int Nf, int K,
                     int flags, float* C, const float* res, const float* res2,
                     const float* acbuf, const int* swapidx,
                     const float* rbfA, const float* rbfWp,
                     __nv_bfloat16* Oh, __nv_bfloat16* Ol) {
        dim3 grid(Nf / 128, (M + 127) / 128);
        bgemm<8, 0><<<grid, 256, SMEM8>>>(Ahp, Alp, wBh + woff, wBl + woff, M, Nf, K, flags,
                                          C, res, res2, acbuf, swapidx, rbfA, rbfWp,
                                          nullptr, nullptr, Oh, Ol);
    };
    auto tc64 = [&](const __nv_bfloat16* Ahp, const __nv_bfloat16* Alp, long woff,
                    int M, int Nf, int K,
                    int flags, float* C, __nv_bfloat16* Oh, __nv_bfloat16* Ol) {
        dim3 grid(Nf / 64, (M + 127) / 128);
        bgemm<4, 0><<<grid, 256, SMEM4>>>(Ahp, Alp, wBh + woff, wBl + woff, M, Nf, K, flags,
                                          C, nullptr, nullptr, nullptr, nullptr, nullptr,
                                          nullptr, nullptr, nullptr, Oh, Ol);
    };

    // ---- batched weight conversion (one launch) ----
    {
        WPtrs w;
        w.p[0] = W_dense_ca;
        w.p[1] = W_ba;
        w.p[2] = W_down;
        w.p[3] = W_bil;
        w.p[4] = W_up_ca;
        w.p[5] = W_up_ac;
        w.p[6] = W_res_b;
        w.p[7] = W_res_b + 262144;
        w.p[8] = W_res_a;
        w.p[9] = W_res_a + 262144;
        w.p[10] = W_res_a + 524288;
        w.p[11] = W_res_a + 786432;
        w.p[12] = W_concat + 131072;   // W3 = rows 256..767 of W_concat (K=512)
        w.p[13] = W_res_m;
        w.p[14] = W_res_m + 262144;
        dim3 grid((262144 + 255) / 256, 15);
        convAllW<<<grid, 256>>>(w, wBh, wBl);
    }
    // ---- m -> H0 hi/lo ----
    convertA_kernel<<<(unsigned)gME, TB>>>(m_in, H0h, H0l, nME);
    // ---- skip branch -> pA ----
    tc128(H0h, H0l, OFF_DENSE, nE, 512, 512, F_ACT | F_F32, pA, nullptr, nullptr, nullptr,
          nullptr, nullptr, nullptr, nullptr, nullptr);
    // ---- x_ba = act(m@W_ba) * (rbf3@W_rbf3) -> H1 (rbf MLP fused) ----
    tc128(H0h, H0l, OFF_BA, nE, 512, 512, F_ACT | F_RBF | F_BF, nullptr, nullptr, nullptr,
          nullptr, nullptr, rbf3, W_rbf3, H1h, H1l);
    // ---- down ----
    tc64(H1h, H1l, OFF_DOWN, nE, 64, 512, F_ACT | F_F32, pdown, nullptr, nullptr);
    // ---- triplet -> rW (hi/lo in H0, width 1024) ----
    triplet_kernel<<<(nE + 1) / 2, 128>>>(pdown, sph, cbfW1, id3_ba, H0h, H0l, nE);
    // ---- bilinear -> H1 (width 64) ----
    tc64(H0h, H0l, OFF_BIL, nE, 64, 1024, F_BF, nullptr, H1h, H1l);
    // ---- up_ac (must precede fused combine) ----
    tc128(H1h, H1l, OFF_UPAC, nE, 512, 64, F_ACT | F_F32, pupac, nullptr, nullptr, nullptr,
          nullptr, nullptr, nullptr, nullptr, nullptr);
    // ---- up_ca with fused combine -> pC + H0 ----
    tc128(H1h, H1l, OFF_UPCA, nE, 512, 64, F_ACT | F_CMB | F_F32 | F_BF, pC, pA, nullptr,
          pupac, id_swap, nullptr, nullptr, H0h, H0l);
    // ---- residual before; 2nd GEMM fuses m_new = (m + (pC + act)*s)*s ----
    tc128(H0h, H0l, OFF_RESB0, nE, 512, 512, F_ACT | F_BF, nullptr, nullptr, nullptr, nullptr,
          nullptr, nullptr, nullptr, H1h, H1l);
    tc128(H1h, H1l, OFF_RESB1, nE, 512, 512, F_ACT | F_RES | F_RES2 | F_F32 | F_BF, pmnew,
          pC, m_in, nullptr, nullptr, nullptr, nullptr, H0h, H0l);
    // ---- residual after x2 ----
    tc128(H0h, H0l, OFF_RESA0, nE, 512, 512, F_ACT | F_BF, nullptr, nullptr, nullptr, nullptr,
          nullptr, nullptr, nullptr, H1h, H1l);
    tc128(H1h, H1l, OFF_RESA1, nE, 512, 512, F_ACT | F_RES | F_F32 | F_BF, pmnew, pmnew,
          nullptr, nullptr, nullptr, nullptr, nullptr, H0h, H0l);
    tc128(H0h, H0l, OFF_RESA2, nE, 512, 512, F_ACT | F_BF, nullptr, nullptr, nullptr, nullptr,
          nullptr, nullptr, nullptr, H1h, H1l);
    tc128(H1h, H1l, OFF_RESA3, nE, 512, 512, F_ACT | F_RES | F_F32 | F_BF, pmnew, pmnew,
          nullptr, nullptr, nullptr, nullptr, nullptr, H0h, H0l);
    // ---- atom update: fused rbf_h MLP + scatter ----
    long nAtomE = (long)nA * E_DIM;
    zero_kernel<<<(unsigned)((nAtomE + TB - 1) / TB), TB>>>(patom, nAtomE);
    {
        dim3 grid((nE + 63) / 64, 2);
        scatter_fused<<<grid, 256>>>(pmnew, rbf_h, W_rbf_hW, id_a, patom, nE);
    }
    sg(patom, W_atom_d, patomB, nA, A_DIM, E_DIM, F_ACT);
    for (int i = 0; i < 3; i++) {
        sg(patomB, W_atom_r + (long)i * 2 * 16384, patomC, nA, A_DIM, A_DIM, F_ACT);
        sg(patomC, W_atom_r + (long)i * 2 * 16384 + 16384, patomB, nA, A_DIM, A_DIM,
           F_ACT | F_RES, patomB);
    }
    long nAA = (long)nA * A_DIM;
    hnew_kernel<<<(unsigned)((nAA + TB - 1) / TB), TB>>>(h_in, patomB, phnew, out, nAA);
    // ---- edge embedding: hp1 = h_new@W1 -> patom, hp2 = h_new@W2 (exact fp32) ----
    sg(phnew, W_concat, patom, nA, 512, 128, 0);
    sg(phnew, W_concat + 65536, php2, nA, 512, 128, 0);
    // ---- concat GEMM (K=512, HP=1): act(m_new@W3 + hp1[id_c] + hp2[id_a]) ----
    {
        dim3 grid(512 / 128, (nE + 127) / 128);
        bgemm<8, 1><<<grid, 256, SMEM8>>>(H0h, H0l, wBh + OFF_CONCAT, wBl + OFF_CONCAT,
                                          nE, 512, 512, F_ACT | F_F32 | F_BF,
                                          pA, nullptr, nullptr, patom, id_c,
                                          nullptr, nullptr, id_a, php2, H1h, H1l);
    }
    tc128(H1h, H1l, OFF_RESM0, nE, 512, 512, F_ACT | F_BF, nullptr, nullptr, nullptr, nullptr,
          nullptr, nullptr, nullptr, H0h, H0l);
    // ---- last GEMM fuses m_out = (mnew + (pA + act)*s)*s -> out ----
    tc128(H0h, H0l, OFF_RESM1, nE, 512, 512, F_ACT | F_RES | F_RES2 | F_F32, out + nAA, pA,
          pmnew, nullptr, nullptr, nullptr, nullptr, nullptr, nullptr);
}

// round 17
// speedup vs baseline: 1.0177x; 1.0177x over previous
#include <cuda_runtime.h>
#include <cuda_bf16.h>
#include <cstdint>

#define INV_SQRT2 0.70710678118654752440f

#define E_DIM 512
#define A_DIM 128
#define T_DIM 64
#define R_DIM 16
#define MAX_E 100000
#define MAX_ATOMS 5000

// epilogue flags
#define F_ACT  1
#define F_RES  2
#define F_RES2 4
#define F_F32  8
#define F_BF   16
#define F_CMB  32
#define F_RBF  64

// weight-arena offsets (elements)
#define OFF_DENSE   0L
#define OFF_BA      262144L
#define OFF_DOWN    524288L
#define OFF_BIL     557056L
#define OFF_UPCA    622592L
#define OFF_UPAC    655360L
#define OFF_RESB0   688128L
#define OFF_RESB1   950272L
#define OFF_RESA0   1212416L
#define OFF_RESA1   1474560L
#define OFF_RESA2   1736704L
#define OFF_RESA3   1998848L
#define OFF_CONCAT  2260992L
#define OFF_RESM0   2654208L
#define OFF_RESM1   2916352L
#define W_ARENA     3178496L

// ------------------------------------------------------------------
// Scratch (device globals)
// ------------------------------------------------------------------
__device__ float g_A[(size_t)MAX_E * E_DIM];
__device__ float g_C[(size_t)MAX_E * E_DIM];
__device__ float g_mnew[(size_t)MAX_E * E_DIM];
__device__ float g_upac[(size_t)MAX_E * E_DIM];
__device__ float g_down[(size_t)MAX_E * T_DIM];
__device__ float g_atom[(size_t)MAX_ATOMS * E_DIM];
__device__ float g_hp2[(size_t)MAX_ATOMS * E_DIM];
__device__ float g_atomB[(size_t)MAX_ATOMS * A_DIM];
__device__ float g_atomC[(size_t)MAX_ATOMS * A_DIM];
__device__ float g_hnew[(size_t)MAX_ATOMS * A_DIM];
// bf16 hi/lo ping-pong activation buffers (max width 1024)
__device__ __nv_bfloat16 g_H0h[(size_t)MAX_E * 1024];
__device__ __nv_bfloat16 g_H0l[(size_t)MAX_E * 1024];
__device__ __nv_bfloat16 g_H1h[(size_t)MAX_E * 1024];
__device__ __nv_bfloat16 g_H1l[(size_t)MAX_E * 1024];
// transposed split weight arena [N][K] per weight
__device__ __nv_bfloat16 g_wBh[W_ARENA];
__device__ __nv_bfloat16 g_wBl[W_ARENA];

// ------------------------------------------------------------------
// Helpers
// ------------------------------------------------------------------
__device__ __forceinline__ float actf(float x) {
    return x * (1.0f / 0.6f) / (1.0f + __expf(-x));
}
__device__ __forceinline__ void split1(float v, __nv_bfloat16& h, __nv_bfloat16& l) {
    h = __float2bfloat16(v);
    l = __float2bfloat16(v - __bfloat162float(h));
}
__device__ __forceinline__ uint32_t smem_u32(const void* p) {
    uint32_t a;
    asm("{ .reg .u64 t; cvta.to.shared.u64 t, %1; cvt.u32.u64 %0, t; }" : "=r"(a) : "l"(p));
    return a;
}
__device__ __forceinline__ void ldm_x4(uint32_t& r0, uint32_t& r1, uint32_t& r2, uint32_t& r3, uint32_t a) {
    asm volatile("ldmatrix.sync.aligned.m8n8.x4.shared.b16 {%0,%1,%2,%3}, [%4];"
                 : "=r"(r0), "=r"(r1), "=r"(r2), "=r"(r3) : "r"(a));
}
__device__ __forceinline__ void mma_bf16(float* c, const uint32_t* a, const uint32_t* b) {
    asm volatile(
        "mma.sync.aligned.m16n8k16.row.col.f32.bf16.bf16.f32 "
        "{%0,%1,%2,%3}, {%4,%5,%6,%7}, {%8,%9}, {%0,%1,%2,%3};"
        : "+f"(c[0]), "+f"(c[1]), "+f"(c[2]), "+f"(c[3])
        : "r"(a[0]), "r"(a[1]), "r"(a[2]), "r"(a[3]), "r"(b[0]), "r"(b[1]));
}
__device__ __forceinline__ void cpa16(uint32_t dst, const void* src) {
    asm volatile("cp.async.cg.shared.global [%0], [%1], 16;" :: "r"(dst), "l"(src));
}
#define CP_COMMIT() asm volatile("cp.async.commit_group;" ::: "memory")
#define CP_WAIT(n)  asm volatile("cp.async.wait_group %0;" :: "n"(n) : "memory")

__device__ __forceinline__ unsigned long long pk2(float v) {
    unsigned long long r;
    unsigned u = __float_as_uint(v);
    asm("mov.b64 %0, {%1, %2};" : "=l"(r) : "r"(u), "r"(u));
    return r;
}
__device__ __forceinline__ void fma2(unsigned long long& a, unsigned long long x, unsigned long long y) {
    asm("fma.rn.f32x2 %0, %1, %2, %0;" : "+l"(a) : "l"(x), "l"(y));
}
__device__ __forceinline__ float2 up2(unsigned long long v) {
    unsigned lo, hi;
    asm("mov.b64 {%0, %1}, %2;" : "=r"(lo), "=r"(hi) : "l"(v));
    return make_float2(__uint_as_float(lo), __uint_as_float(hi));
}

// ------------------------------------------------------------------
// HMMA split-bf16 GEMM, cp.async 2-stage pipeline, 2 CTAs/SM.
// HP is a COMPILE-TIME flag: HP=0 instantiations compile identically
// to the proven kernel; HP=1 only for the concat launch.
// ------------------------------------------------------------------
template <int NT, int HP>
__global__ void __launch_bounds__(256, 2) bgemm(
    const __nv_bfloat16* __restrict__ Ah, const __nv_bfloat16* __restrict__ Al,
    const __nv_bfloat16* __restrict__ Bh, const __nv_bfloat16* __restrict__ Bl,
    int M, int Nfull, int K, int flags,
    float* __restrict__ C, const float* __restrict__ res, const float* __restrict__ res2,
    const float* __restrict__ acbuf, const int* __restrict__ swapidx,
    const float* __restrict__ rbfA, const float* __restrict__ rbfW,
    const int* __restrict__ ida, const float* __restrict__ hp2,
    __nv_bfloat16* __restrict__ Ohi, __nv_bfloat16* __restrict__ Olo)
{
    constexpr int BN = NT * 16;
    constexpr int AS_ELE = 128 * 40;
    constexpr int BS_ELE = BN * 40;
    constexpr int STAGE = 2 * AS_ELE + 2 * BS_ELE;   // elements
    constexpr int BITER = (BN * 4) / 256;
    extern __shared__ __nv_bfloat16 sm[];

    const int tid = threadIdx.x;
    const int lane = tid & 31, wid = tid >> 5;
    const int wm = (wid & 3) * 32;
    const int wn = (wid >> 2) * (NT * 8);
    const long brow = (long)blockIdx.y * 128;
    const long bcol = (long)blockIdx.x * BN;
    const uint32_t smb = smem_u32(sm);

    // ---- hoisted load addressing ----
    int ar0 = tid >> 2, aj = (tid & 3) * 8;
    int ar1 = ar0 + 64;
    long gr0 = brow + ar0; if (gr0 > (long)(M - 1)) gr0 = M - 1;
    long gr1 = brow + ar1; if (gr1 > (long)(M - 1)) gr1 = M - 1;
    const __nv_bfloat16* sAh0 = Ah + gr0 * (long)K + aj;
    const __nv_bfloat16* sAl0 = Al + gr0 * (long)K + aj;
    const __nv_bfloat16* sAh1 = Ah + gr1 * (long)K + aj;
    const __nv_bfloat16* sAl1 = Al + gr1 * (long)K + aj;
    const uint32_t dA0 = (uint32_t)(ar0 * 40) + aj;
    const uint32_t dA1 = (uint32_t)(ar1 * 40) + aj;
    const __nv_bfloat16* sBh[BITER];
    const __nv_bfloat16* sBl[BITER];
    uint32_t dB[BITER];
#pragma unroll
    for (int it = 0; it < BITER; it++) {
        int idx = tid + it * 256;
        int r = idx >> 2, j = (idx & 3) * 8;
        long gn = bcol + r;
        sBh[it] = Bh + gn * (long)K + j;
        sBl[it] = Bl + gn * (long)K + j;
        dB[it] = (uint32_t)(r * 40) + j;
    }

    auto load_chunk = [&](int k0, int s) {
        uint32_t sb = smb + (uint32_t)s * (STAGE * 2);
        cpa16(sb + dA0 * 2, sAh0 + k0);
        cpa16(sb + (AS_ELE + dA0) * 2, sAl0 + k0);
        cpa16(sb + dA1 * 2, sAh1 + k0);
        cpa16(sb + (AS_ELE + dA1) * 2, sAl1 + k0);
#pragma unroll
        for (int it = 0; it < BITER; it++) {
            cpa16(sb + (2 * AS_ELE + dB[it]) * 2, sBh[it] + k0);
            cpa16(sb + (2 * AS_ELE + BS_ELE + dB[it]) * 2, sBl[it] + k0);
        }
    };

    // ---- hoisted compute addressing ----
    const uint32_t aOff = (uint32_t)((wm + (lane & 15)) * 40) + (((lane >> 4) & 1) << 3);
    const uint32_t bOff = (uint32_t)((wn + (lane & 7) + (((lane >> 4) & 1) << 3)) * 40)
                        + (((lane >> 3) & 1) << 3);
    const uint32_t aB0 = smb + aOff * 2;
    const uint32_t aB1 = aB0 + STAGE * 2;
    const uint32_t bB0 = smb + (2 * AS_ELE + bOff) * 2;
    const uint32_t bB1 = bB0 + STAGE * 2;

    float acc[2][NT][4];
#pragma unroll
    for (int i = 0; i < 2; i++)
#pragma unroll
        for (int j = 0; j < NT; j++)
#pragma unroll
            for (int t = 0; t < 4; t++) acc[i][j][t] = 0.f;

    const int nc = K >> 5;

    load_chunk(0, 0);
    CP_COMMIT();

    for (int i = 0; i < nc; i++) {
        if (i + 1 < nc) {
            load_chunk((i + 1) << 5, (i + 1) & 1);
            CP_COMMIT();
            CP_WAIT(1);
        } else {
            CP_WAIT(0);
        }
        __syncthreads();

        const uint32_t aH = (i & 1) ? aB1 : aB0;
        const uint32_t bH = (i & 1) ? bB1 : bB0;

#pragma unroll
        for (int ks = 0; ks < 32; ks += 16) {
            uint32_t ah[2][4], al[2][4];
#pragma unroll
            for (int mt = 0; mt < 2; mt++) {
                ldm_x4(ah[mt][0], ah[mt][1], ah[mt][2], ah[mt][3],
                       aH + (mt * 640 + ks) * 2);
                ldm_x4(al[mt][0], al[mt][1], al[mt][2], al[mt][3],
                       aH + (AS_ELE + mt * 640 + ks) * 2);
            }
#pragma unroll
            for (int ntp = 0; ntp < NT; ntp += 2) {
                uint32_t bh[4], bl[4];
                ldm_x4(bh[0], bh[1], bh[2], bh[3], bH + (ntp * 320 + ks) * 2);
                ldm_x4(bl[0], bl[1], bl[2], bl[3], bH + (BS_ELE + ntp * 320 + ks) * 2);
                // term-major, mt-interleaved: same-acc reuse distance = 4
                mma_bf16(acc[0][ntp],     ah[0], bh);
                mma_bf16(acc[1][ntp],     ah[1], bh);
                mma_bf16(acc[0][ntp + 1], ah[0], bh + 2);
                mma_bf16(acc[1][ntp + 1], ah[1], bh + 2);
                mma_bf16(acc[0][ntp],     ah[0], bl);
                mma_bf16(acc[1][ntp],     ah[1], bl);
                mma_bf16(acc[0][ntp + 1], ah[0], bl + 2);
                mma_bf16(acc[1][ntp + 1], ah[1], bl + 2);
                mma_bf16(acc[0][ntp],     al[0], bh);
                mma_bf16(acc[1][ntp],     al[1], bh);
                mma_bf16(acc[0][ntp + 1], al[0], bh + 2);
                mma_bf16(acc[1][ntp + 1], al[1], bh + 2);
            }
        }
        __syncthreads();
    }

    // ---- optional rbf SMEM tiles (post-mainloop; SMEM reused) ----
    float* srbf = (float*)sm;            // [128][16]
    float* sW   = (float*)sm + 2048;     // [16][BN]
    if (flags & F_RBF) {
        for (int idx = tid; idx < 2048; idx += 256) {
            int r = idx >> 4, t = idx & 15;
            long gr = brow + r;
            if (gr > (long)(M - 1)) gr = M - 1;
            srbf[idx] = rbfA[gr * 16 + t];
        }
        for (int idx = tid; idx < 16 * BN; idx += 256) {
            int t = idx / BN, c = idx - t * BN;
            sW[idx] = rbfW[(long)t * Nfull + bcol + c];
        }
        __syncthreads();
    }

    // ---- epilogue ----
#pragma unroll
    for (int mt = 0; mt < 2; mt++) {
#pragma unroll
        for (int nt = 0; nt < NT; nt++) {
            int lcol = wn + nt * 8 + (lane & 3) * 2;
            long col = bcol + lcol;
#pragma unroll
            for (int half = 0; half < 2; half++) {
                int lrow = wm + mt * 16 + (lane >> 2) + half * 8;
                long row = brow + lrow;
                if (row >= M) continue;
                float vx = acc[mt][nt][half * 2];
                float vy = acc[mt][nt][half * 2 + 1];
                long base = row * (long)Nfull + col;
                if (HP) {
                    long b1 = (long)swapidx[row] * Nfull + col;   // id_c gather -> hp1
                    long b2 = (long)ida[row] * Nfull + col;       // id_a gather -> hp2
                    float2 u = *(const float2*)&acbuf[b1];
                    float2 w = *(const float2*)&hp2[b2];
                    vx += u.x + w.x;
                    vy += u.y + w.y;
                }
                if (flags & F_ACT) { vx = actf(vx); vy = actf(vy); }
                if (flags & F_RBF) {
                    float rwx = 0.f, rwy = 0.f;
#pragma unroll
                    for (int t = 0; t < 16; t++) {
                        float rv = srbf[lrow * 16 + t];
                        rwx += rv * sW[t * BN + lcol];
                        rwy += rv * sW[t * BN + lcol + 1];
                    }
                    vx *= rwx; vy *= rwy;
                }
                if (flags & F_CMB) {
                    long sbase = (long)swapidx[row] * Nfull + col;
                    float2 a = *(const float2*)&acbuf[sbase];
                    float2 r = *(const float2*)&res[base];
                    vx = (r.x + (vx + a.x) * INV_SQRT2) * INV_SQRT2;
                    vy = (r.y + (vy + a.y) * INV_SQRT2) * INV_SQRT2;
                }
                if (flags & F_RES) {
                    float2 r = *(const float2*)&res[base];
                    vx = (r.x + vx) * INV_SQRT2;
                    vy = (r.y + vy) * INV_SQRT2;
                }
                if (flags & F_RES2) {
                    float2 r = *(const float2*)&res2[base];
                    vx = (r.x + vx) * INV_SQRT2;
                    vy = (r.y + vy) * INV_SQRT2;
                }
                if (flags & F_F32) *(float2*)&C[base] = make_float2(vx, vy);
                if (flags & F_BF) {
                    __nv_bfloat16 h0, l0, h1, l1;
                    split1(vx, h0, l0); split1(vy, h1, l1);
                    __nv_bfloat162 hp(h0, h1), lp(l0, l1);
                    *(__nv_bfloat162*)&Ohi[base] = hp;
                    *(__nv_bfloat162*)&Olo[base] = lp;
                }
            }
        }
    }
}

// ------------------------------------------------------------------
// fp32 SGEMM (small GEMMs): C = epi(A @ B)
// ------------------------------------------------------------------
__global__ void __launch_bounds__(256, 2) sgemm_kernel(
    const float* __restrict__ A, const float* __restrict__ B, float* __restrict__ C,
    int M, int N, int K, int flags,
    const float* __restrict__ res)
{
    __shared__ __align__(16) float As[8][128];
    __shared__ __align__(16) float Bs[8][128];
    int tid = threadIdx.x;
    int tx = tid & 15, ty = tid >> 4;
    long brow = (long)blockIdx.y * 128;
    long bcol = (long)blockIdx.x * 128;

    unsigned long long acc[8][4];
#pragma unroll
    for (int i = 0; i < 8; i++)
#pragma unroll
        for (int j = 0; j < 4; j++) acc[i][j] = 0ull;

    int aRow = tid >> 1, aCol = (tid & 1) * 4;
    int bRow = tid >> 5, bCol = (tid & 31) * 4;
    long aGr = brow + aRow;
    long bGc = bcol + bCol;

    for (int k0 = 0; k0 < K; k0 += 8) {
        float4 av = make_float4(0.f, 0.f, 0.f, 0.f);
        if (aGr < M) av = *reinterpret_cast<const float4*>(A + aGr * (long)K + (k0 + aCol));
        As[aCol + 0][aRow] = av.x;
        As[aCol + 1][aRow] = av.y;
        As[aCol + 2][aRow] = av.z;
        As[aCol + 3][aRow] = av.w;
        float4 bv = make_float4(0.f, 0.f, 0.f, 0.f);
        if (bGc < N) bv = *reinterpret_cast<const float4*>(B + (long)(k0 + bRow) * N + bGc);
        *reinterpret_cast<float4*>(&Bs[bRow][bCol]) = bv;
        __syncthreads();
#pragma unroll
        for (int kk = 0; kk < 8; kk++) {
            float4 a0 = *reinterpret_cast<const float4*>(&As[kk][ty * 8]);
            float4 a1 = *reinterpret_cast<const float4*>(&As[kk][ty * 8 + 4]);
            ulonglong2 b0 = *reinterpret_cast<const ulonglong2*>(&Bs[kk][tx * 8]);
            ulonglong2 b1 = *reinterpret_cast<const ulonglong2*>(&Bs[kk][tx * 8 + 4]);
            unsigned long long bb[4] = {b0.x, b0.y, b1.x, b1.y};
            float ra[8] = {a0.x, a0.y, a0.z, a0.w, a1.x, a1.y, a1.z, a1.w};
#pragma unroll
            for (int i = 0; i < 8; i++) {
                unsigned long long a2 = pk2(ra[i]);
#pragma unroll
                for (int j = 0; j < 4; j++) fma2(acc[i][j], a2, bb[j]);
            }
        }
        __syncthreads();
    }

#pragma unroll
    for (int i = 0; i < 8; i++) {
        long row = brow + ty * 8 + i;
        if (row >= M) continue;
#pragma unroll
        for (int j = 0; j < 4; j++) {
            long col = bcol + tx * 8 + j * 2;
            if (col >= N) continue;
            float2 v = up2(acc[i][j]);
            long idx = row * (long)N + col;
            if (flags & F_ACT) { v.x = actf(v.x); v.y = actf(v.y); }
            if (flags & F_RES) {
                v.x = (res[idx] + v.x) * INV_SQRT2;
                v.y = (res[idx + 1] + v.y) * INV_SQRT2;
            }
            C[idx] = v.x;
            C[idx + 1] = v.y;
        }
    }
}

// ------------------------------------------------------------------
// Conversions
// ------------------------------------------------------------------
__global__ void convertA_kernel(const float* __restrict__ x,
                                __nv_bfloat16* __restrict__ hi, __nv_bfloat16* __restrict__ lo, long n)
{
    long i = (long)blockIdx.x * blockDim.x + threadIdx.x;
    if (i >= n) return;
    __nv_bfloat16 h, l;
    split1(x[i], h, l);
    hi[i] = h; lo[i] = l;
}

// Batched weight conversion: all 15 weights in one launch.
struct WPtrs { const float* p[15]; };

__global__ void convAllW(WPtrs w, __nv_bfloat16* __restrict__ hi, __nv_bfloat16* __restrict__ lo)
{
    static const int KT[15] = {512, 512, 512, 1024, 64, 64, 512, 512, 512, 512, 512, 512, 512, 512, 512};
    static const int NT_[15] = {512, 512, 64, 64, 512, 512, 512, 512, 512, 512, 512, 512, 512, 512, 512};
    static const long OFF[15] = {OFF_DENSE, OFF_BA, OFF_DOWN, OFF_BIL, OFF_UPCA, OFF_UPAC,
                                 OFF_RESB0, OFF_RESB1, OFF_RESA0, OFF_RESA1, OFF_RESA2, OFF_RESA3,
                                 OFF_CONCAT, OFF_RESM0, OFF_RESM1};
    int j = blockIdx.y;
    int K = KT[j], N = NT_[j];
    long tot = (long)K * N;
    long i = (long)blockIdx.x * blockDim.x + threadIdx.x;
    if (i >= tot) return;
    int n = (int)(i / K), k = (int)(i - (long)n * K);
    __nv_bfloat16 h, l;
    split1(w.p[j][(long)k * N + n], h, l);
    hi[OFF[j] + i] = h;
    lo[OFF[j] + i] = l;
}

// ------------------------------------------------------------------
// Triplet kernel: 2 edges per block (128 threads); packed uint4 stores.
// ------------------------------------------------------------------
__global__ void __launch_bounds__(128) triplet_kernel(
    const float* __restrict__ xd, const float* __restrict__ sph,
    const float* __restrict__ cW, const int* __restrict__ ba,
    __nv_bfloat16* __restrict__ rWh, __nv_bfloat16* __restrict__ rWl, int nE)
{
    const int g = threadIdx.x >> 6;      // edge slot 0/1
    const int t = threadIdx.x & 63;
    const long e = (long)blockIdx.x * 2 + g;

    __shared__ float s_sph[2][70];
    __shared__ float s_cW[2][112];
    __shared__ int s_ba[2][10];

    if (e < nE) {
        if (t < 10) s_ba[g][t] = ba[e * 10 + t];
        for (int i = t; i < 70; i += 64) s_sph[g][i] = sph[e * 70 + i];
        for (int i = t; i < 112; i += 64) s_cW[g][i] = cW[e * 112 + i];
    }
    __syncthreads();
    if (e >= nE) return;

    float xv[10];
#pragma unroll
    for (int k = 0; k < 10; k++)
        xv[k] = xd[(long)s_ba[g][k] * 64 + t];

    float sk[7];
#pragma unroll
    for (int s = 0; s < 7; s++) {
        float a = 0.f;
#pragma unroll
        for (int k = 0; k < 10; k++) a += s_sph[g][k * 7 + s] * xv[k];
        sk[s] = a;
    }

    __nv_bfloat16 hbuf[16], lbuf[16];
#pragma unroll
    for (int j = 0; j < 16; j++) {
        float a = 0.f;
#pragma unroll
        for (int s = 0; s < 7; s++) a += s_cW[g][j * 7 + s] * sk[s];
        split1(a, hbuf[j], lbuf[j]);
    }
    long ob = e * 1024 + t * 16;
    *(uint4*)&rWh[ob]     = *(uint4*)&hbuf[0];
    *(uint4*)&rWh[ob + 8] = *(uint4*)&hbuf[8];
    *(uint4*)&rWl[ob]     = *(uint4*)&lbuf[0];
    *(uint4*)&rWl[ob + 8] = *(uint4*)&lbuf[8];
}

// ------------------------------------------------------------------
// Fused rbf_h MLP + scatter
// ------------------------------------------------------------------
__global__ void __launch_bounds__(256) scatter_fused(
    const float* __restrict__ mnew, const float* __restrict__ rbf_h,
    const float* __restrict__ W,   // [16][512]
    const int* __restrict__ id_a, float* __restrict__ atom, int nE)
{
    __shared__ float sW[16 * 256];
    __shared__ float srbf[64 * 16];
    __shared__ int sida[64];

    const int tid = threadIdx.x;
    const int chalf = blockIdx.y;
    const long e0 = (long)blockIdx.x * 64;

    for (int idx = tid; idx < 4096; idx += 256) {
        int t = idx >> 8, c = idx & 255;
        sW[idx] = W[t * 512 + chalf * 256 + c];
    }
    for (int idx = tid; idx < 1024; idx += 256) {
        int el = idx >> 4, t = idx & 15;
        long eg = e0 + el;
        srbf[idx] = (eg < nE) ? rbf_h[eg * 16 + t] : 0.f;
    }
    if (tid < 64) {
        long eg = e0 + tid;
        sida[tid] = (eg < nE) ? id_a[eg] : 0;
    }
    __syncthreads();

    const int c = tid;
    int nel = (int)(((long)nE - e0) < 64 ? (nE - e0) : 64);
    for (int el = 0; el < nel; el++) {
        long eg = e0 + el;
        float rw = 0.f;
#pragma unroll
        for (int t = 0; t < 16; t++) rw += srbf[el * 16 + t] * sW[t * 256 + c];
        float v = mnew[eg * 512 + chalf * 256 + c] * rw;
        atomicAdd(&atom[(long)sida[el] * 512 + chalf * 256 + c], v);
    }
}

// ------------------------------------------------------------------
// Remaining elementwise kernels
// ------------------------------------------------------------------
__global__ void zero_kernel(float* __restrict__ p, long n)
{
    long i = (long)blockIdx.x * blockDim.x + threadIdx.x;
    if (i < n) p[i] = 0.f;
}

__global__ void hnew_kernel(const float* __restrict__ h, const float* __restrict__ xa,
                            float* __restrict__ hnew, float* __restrict__ out, long n)
{
    long i = (long)blockIdx.x * blockDim.x + threadIdx.x;
    if (i >= n) return;
    float v = (h[i] + xa[i]) * INV_SQRT2;
    hnew[i] = v;
    out[i] = v;
}

// ------------------------------------------------------------------
// Host orchestration
// ------------------------------------------------------------------
static inline void sg(const float* A, const float* B, float* C, int M, int N, int K,
                      int flags, const float* res = nullptr)
{
    dim3 grid((N + 127) / 128, (M + 127) / 128);
    sgemm_kernel<<<grid, 256>>>(A, B, C, M, N, K, flags, res);
}

#define SMEM8 ((2 * 128 * 40 + 2 * 128 * 40) * 2 * 2)  // 81920 B
#define SMEM4 ((2 * 128 * 40 + 2 * 64 * 40) * 2 * 2)   // 61440 B

extern "C" void kernel_launch(void* const* d_in, const int* in_sizes, int n_in,
                              void* d_out, int out_size)
{
    const float* h_in       = (const float*)d_in[0];
    const float* m_in       = (const float*)d_in[1];
    const float* rbf3       = (const float*)d_in[2];
    const float* cbfW1      = (const float*)d_in[3];
    const float* sph        = (const float*)d_in[4];
    const float* rbf_h      = (const float*)d_in[5];
    const float* W_dense_ca = (const float*)d_in[6];
    const float* W_ba       = (const float*)d_in[7];
    const float* W_rbf3     = (const float*)d_in[8];
    const float* W_down     = (const float*)d_in[9];
    const float* W_bil      = (const float*)d_in[10];
    const float* W_up_ca    = (const float*)d_in[11];
    const float* W_up_ac    = (const float*)d_in[12];
    const float* W_res_b    = (const float*)d_in[13];
    const float* W_res_a    = (const float*)d_in[14];
    const float* W_rbf_hW   = (const float*)d_in[15];
    const float* W_atom_d   = (const float*)d_in[16];
    const float* W_atom_r   = (const float*)d_in[17];
    const float* W_concat   = (const float*)d_in[18];
    const float* W_res_m    = (const float*)d_in[19];
    const int* id_swap = (const int*)d_in[21];
    const int* id3_ba  = (const int*)d_in[22];
    const int* id_c    = (const int*)d_in[24];
    const int* id_a    = (const int*)d_in[25];

    int nE = in_sizes[1] / E_DIM;
    int nA = in_sizes[0] / A_DIM;
    float* out = (float*)d_out;

    float *pA, *pC, *pmnew, *pupac, *pdown;
    float *patom, *php2, *patomB, *patomC, *phnew;
    __nv_bfloat16 *H0h, *H0l, *H1h, *H1l, *wBh, *wBl;
    cudaGetSymbolAddress((void**)&pA, g_A);
    cudaGetSymbolAddress((void**)&pC, g_C);
    cudaGetSymbolAddress((void**)&pmnew, g_mnew);
    cudaGetSymbolAddress((void**)&pupac, g_upac);
    cudaGetSymbolAddress((void**)&pdown, g_down);
    cudaGetSymbolAddress((void**)&patom, g_atom);
    cudaGetSymbolAddress((void**)&php2, g_hp2);
    cudaGetSymbolAddress((void**)&patomB, g_atomB);
    cudaGetSymbolAddress((void**)&patomC, g_atomC);
    cudaGetSymbolAddress((void**)&phnew, g_hnew);
    cudaGetSymbolAddress((void**)&H0h, g_H0h);
    cudaGetSymbolAddress((void**)&H0l, g_H0l);
    cudaGetSymbolAddress((void**)&H1h, g_H1h);
    cudaGetSymbolAddress((void**)&H1l, g_H1l);
    cudaGetSymbolAddress((void**)&wBh, g_wBh);
    cudaGetSymbolAddress((void**)&wBl, g_wBl);

    cudaFuncSetAttribute((bgemm<8, 0>), cudaFuncAttributeMaxDynamicSharedMemorySize, SMEM8);
    cudaFuncSetAttribute((bgemm<8, 1>), cudaFuncAttributeMaxDynamicSharedMemorySize, SMEM8);
    cudaFuncSetAttribute((bgemm<4, 0>), cudaFuncAttributeMaxDynamicSharedMemorySize, SMEM4);

    long nME = (long)nE * E_DIM;
    int TB = 256;
    long gME = (nME + TB - 1) / TB;

    auto tc128 = [&](const __nv_bfloat16* Ahp, const __nv_bfloat16* Alp, long woff,
                     int M, int Nf, int K,
                     int flags, float* C, const float* res, const float* res2,
                     const float* acbuf, const int* swapidx,
                     const float* rbfA, const float* rbfWp,
                     __nv_bfloat16* Oh, __nv_bfloat16* Ol) {
        dim3 grid(Nf / 128, (M + 127) / 128);
        bgemm<8, 0><<<grid, 256, SMEM8>>>(Ahp, Alp, wBh + woff, wBl + woff, M, Nf, K, flags,
                                          C, res, res2, acbuf, swapidx, rbfA, rbfWp,
                                          nullptr, nullptr, Oh, Ol);
    };
    auto tc64 = [&](const __nv_bfloat16* Ahp, const __nv_bfloat16* Alp, long woff,
                    int M, int Nf, int K,
                    int flags, float* C, __nv_bfloat16* Oh, __nv_bfloat16* Ol) {
        dim3 grid(Nf / 64, (M + 127) / 128);
        bgemm<4, 0><<<grid, 256, SMEM4>>>(Ahp, Alp, wBh + woff, wBl + woff, M, Nf, K, flags,
                                          C, nullptr, nullptr, nullptr, nullptr, nullptr,
                                          nullptr, nullptr, nullptr, Oh, Ol);
    };

    // ---- batched weight conversion (one launch) ----
    {
        WPtrs w;
        w.p[0] = W_dense_ca;
        w.p[1] = W_ba;
        w.p[2] = W_down;
        w.p[3] = W_bil;
        w.p[4] = W_up_ca;
        w.p[5] = W_up_ac;
        w.p[6] = W_res_b;
        w.p[7] = W_res_b + 262144;
        w.p[8] = W_res_a;
        w.p[9] = W_res_a + 262144;
        w.p[10] = W_res_a + 524288;
        w.p[11] = W_res_a + 786432;
        w.p[12] = W_concat + 131072;   // W3 = rows 256..767 of W_concat (K=512)
        w.p[13] = W_res_m;
        w.p[14] = W_res_m + 262144;
        dim3 grid((262144 + 255) / 256, 15);
        convAllW<<<grid, 256>>>(w, wBh, wBl);
    }
    // ---- m -> H0 hi/lo ----
    convertA_kernel<<<(unsigned)gME, TB>>>(m_in, H0h, H0l, nME);
    // ---- skip branch -> pA ----
    tc128(H0h, H0l, OFF_DENSE, nE, 512, 512, F_ACT | F_F32, pA, nullptr, nullptr, nullptr,
          nullptr, nullptr, nullptr, nullptr, nullptr);
    // ---- x_ba = act(m@W_ba) * (rbf3@W_rbf3) -> H1 (rbf MLP fused) ----
    tc128(H0h, H0l, OFF_BA, nE, 512, 512, F_ACT | F_RBF | F_BF, nullptr, nullptr, nullptr,
          nullptr, nullptr, rbf3, W_rbf3, H1h, H1l);
    // ---- down ----
    tc64(H1h, H1l, OFF_DOWN, nE, 64, 512, F_ACT | F_F32, pdown, nullptr, nullptr);
    // ---- triplet -> rW (hi/lo in H0, width 1024) ----
    triplet_kernel<<<(nE + 1) / 2, 128>>>(pdown, sph, cbfW1, id3_ba, H0h, H0l, nE);
    // ---- bilinear -> H1 (width 64) ----
    tc64(H0h, H0l, OFF_BIL, nE, 64, 1024, F_BF, nullptr, H1h, H1l);
    // ---- up_ac (must precede fused combine) ----
    tc128(H1h, H1l, OFF_UPAC, nE, 512, 64, F_ACT | F_F32, pupac, nullptr, nullptr, nullptr,
          nullptr, nullptr, nullptr, nullptr, nullptr);
    // ---- up_ca with fused combine -> pC + H0 ----
    tc128(H1h, H1l, OFF_UPCA, nE, 512, 64, F_ACT | F_CMB | F_F32 | F_BF, pC, pA, nullptr,
          pupac, id_swap, nullptr, nullptr, H0h, H0l);
    // ---- residual before; 2nd GEMM fuses m_new = (m + (pC + act)*s)*s ----
    tc128(H0h, H0l, OFF_RESB0, nE, 512, 512, F_ACT | F_BF, nullptr, nullptr, nullptr, nullptr,
          nullptr, nullptr, nullptr, H1h, H1l);
    tc128(H1h, H1l, OFF_RESB1, nE, 512, 512, F_ACT | F_RES | F_RES2 | F_F32 | F_BF, pmnew,
          pC, m_in, nullptr, nullptr, nullptr, nullptr, H0h, H0l);
    // ---- residual after x2 ----
    tc128(H0h, H0l, OFF_RESA0, nE, 512, 512, F_ACT | F_BF, nullptr, nullptr, nullptr, nullptr,
          nullptr, nullptr, nullptr, H1h, H1l);
    tc128(H1h, H1l, OFF_RESA1, nE, 512, 512, F_ACT | F_RES | F_F32 | F_BF, pmnew, pmnew,
          nullptr, nullptr, nullptr, nullptr, nullptr, H0h, H0l);
    tc128(H0h, H0l, OFF_RESA2, nE, 512, 512, F_ACT | F_BF, nullptr, nullptr, nullptr, nullptr,
          nullptr, nullptr, nullptr, H1h, H1l);
    tc128(H1h, H1l, OFF_RESA3, nE, 512, 512, F_ACT | F_RES | F_F32 | F_BF, pmnew, pmnew,
          nullptr, nullptr, nullptr, nullptr, nullptr, H0h, H0l);
    // ---- atom update: fused rbf_h MLP + scatter ----
    long nAtomE = (long)nA * E_DIM;
    zero_kernel<<<(unsigned)((nAtomE + TB - 1) / TB), TB>>>(patom, nAtomE);
    {
        dim3 grid((nE + 63) / 64, 2);
        scatter_fused<<<grid, 256>>>(pmnew, rbf_h, W_rbf_hW, id_a, patom, nE);
    }
    sg(patom, W_atom_d, patomB, nA, A_DIM, E_DIM, F_ACT);
    for (int i = 0; i < 3; i++) {
        sg(patomB, W_atom_r + (long)i * 2 * 16384, patomC, nA, A_DIM, A_DIM, F_ACT);
        sg(patomC, W_atom_r + (long)i * 2 * 16384 + 16384, patomB, nA, A_DIM, A_DIM,
           F_ACT | F_RES, patomB);
    }
    long nAA = (long)nA * A_DIM;
    hnew_kernel<<<(unsigned)((nAA + TB - 1) / TB), TB>>>(h_in, patomB, phnew, out, nAA);
    // ---- edge embedding: hp1 = h_new@W1 -> patom, hp2 = h_new@W2 (exact fp32) ----
    sg(phnew, W_concat, patom, nA, 512, 128, 0);
    sg(phnew, W_concat + 65536, php2, nA, 512, 128, 0);
    // ---- concat GEMM (K=512, HP=1): act(m_new@W3 + hp1[id_c] + hp2[id_a]) ----
    {
        dim3 grid(512 / 128, (nE + 127) / 128);
        bgemm<8, 1><<<grid, 256, SMEM8>>>(H0h, H0l, wBh + OFF_CONCAT, wBl + OFF_CONCAT,
                                          nE, 512, 512, F_ACT | F_F32 | F_BF,
                                          pA, nullptr, nullptr, patom, id_c,
                                          nullptr, nullptr, id_a, php2, H1h, H1l);
    }
    tc128(H1h, H1l, OFF_RESM0, nE, 512, 512, F_ACT | F_BF, nullptr, nullptr, nullptr, nullptr,
          nullptr, nullptr, nullptr, H0h, H0l);
    // ---- last GEMM fuses m_out = (mnew + (pA + act)*s)*s -> out ----
    tc128(H0h, H0l, OFF_RESM1, nE, 512, 512, F_ACT | F_RES | F_RES2 | F_F32, out + nAA, pA,
          pmnew, nullptr, nullptr, nullptr, nullptr, nullptr, nullptr);
}